// round 11
// baseline (speedup 1.0000x reference)
#include <cuda_runtime.h>
#include <cuda_bf16.h>
#include <cuda_fp16.h>
#include <math.h>

typedef __nv_bfloat16 bf16;

// ---------------- problem constants ----------------
#define B_     2
#define I_     2048
#define J_     2048
#define DIM_   1024
#define H_     16
#define DH_    64
#define INNER_ 1024
#define EPS_   1e-5f
#define SCALE_ 0.125f   // DH^-0.5
#define SIMN   134217728   // B*H*I*J
#define NZ_    32          // B*H

// ---------------- scratch (device globals; allocation-free) ----------------
__device__ bf16 g_xnh[B_ * I_ * DIM_],  g_xnl[B_ * I_ * DIM_];
__device__ bf16 g_cnh[B_ * J_ * DIM_],  g_cnl[B_ * J_ * DIM_];
__device__ bf16 g_qkh[B_ * I_ * INNER_], g_qkl[B_ * I_ * INNER_];
__device__ bf16 g_ckh[B_ * J_ * INNER_], g_ckl[B_ * J_ * INNER_];
__device__ half g_vh [B_ * I_ * INNER_], g_vl [B_ * I_ * INNER_];
__device__ half g_cvh[B_ * J_ * INNER_], g_cvl[B_ * J_ * INNER_];
__device__ bf16 g_o1h[B_ * I_ * INNER_], g_o1l[B_ * I_ * INNER_];
__device__ bf16 g_o2h[B_ * J_ * INNER_], g_o2l[B_ * J_ * INNER_];
__device__ bf16 g_wh[6][DIM_ * INNER_], g_wl[6][DIM_ * INNER_];
__device__ half g_sim16[SIMN];                // exp(scale*QK) fp16, 256 MB
__device__ half g_at16[SIMN], g_ct16[SIMN];   // mixed attn, fp16
__device__ float g_rp[NZ_ * I_ * 16], g_cp[NZ_ * J_ * 16];  // tile partial sums
__device__ float g_rs[NZ_ * I_], g_cs[NZ_ * J_];            // 1/rowsum, 1/colsum

// ---------------- helpers ----------------
__device__ __forceinline__ unsigned packsplit(float x, float y, unsigned& lo) {
    bf16 hx = __float2bfloat16(x);
    bf16 hy = __float2bfloat16(y);
    float lx = x - __bfloat162float(hx);
    float ly = y - __bfloat162float(hy);
    __nv_bfloat162 l2 = __floats2bfloat162_rn(lx, ly);
    lo = *(unsigned*)&l2;
    __nv_bfloat162 h2 = __halves2bfloat162(hx, hy);
    return *(unsigned*)&h2;
}
__device__ __forceinline__ unsigned packsplit_h(float x, float y, unsigned& lo) {
    half hx = __float2half(x);
    half hy = __float2half(y);
    float lx = x - __half2float(hx);
    float ly = y - __half2float(hy);
    half2 l2 = __floats2half2_rn(lx, ly);
    lo = *(unsigned*)&l2;
    half2 h2 = __halves2half2(hx, hy);
    return *(unsigned*)&h2;
}
template <class T> struct Mma;
template <> struct Mma<bf16> {
    static __device__ __forceinline__ void op(float* c, const unsigned* a,
                                              const unsigned* b) {
        asm volatile(
            "mma.sync.aligned.m16n8k16.row.col.f32.bf16.bf16.f32 "
            "{%0,%1,%2,%3}, {%4,%5,%6,%7}, {%8,%9}, {%0,%1,%2,%3};\n"
            : "+f"(c[0]), "+f"(c[1]), "+f"(c[2]), "+f"(c[3])
            : "r"(a[0]), "r"(a[1]), "r"(a[2]), "r"(a[3]), "r"(b[0]), "r"(b[1]));
    }
};
template <> struct Mma<half> {
    static __device__ __forceinline__ void op(float* c, const unsigned* a,
                                              const unsigned* b) {
        asm volatile(
            "mma.sync.aligned.m16n8k16.row.col.f32.f16.f16.f32 "
            "{%0,%1,%2,%3}, {%4,%5,%6,%7}, {%8,%9}, {%0,%1,%2,%3};\n"
            : "+f"(c[0]), "+f"(c[1]), "+f"(c[2]), "+f"(c[3])
            : "r"(a[0]), "r"(a[1]), "r"(a[2]), "r"(a[3]), "r"(b[0]), "r"(b[1]));
    }
};
__device__ __forceinline__ void ldsm4(unsigned* d, unsigned a) {
    asm volatile("ldmatrix.sync.aligned.m8n8.x4.shared.b16 {%0,%1,%2,%3},[%4];\n"
                 : "=r"(d[0]), "=r"(d[1]), "=r"(d[2]), "=r"(d[3]) : "r"(a));
}
__device__ __forceinline__ void ldsm4t(unsigned* d, unsigned a) {
    asm volatile("ldmatrix.sync.aligned.m8n8.x4.trans.shared.b16 {%0,%1,%2,%3},[%4];\n"
                 : "=r"(d[0]), "=r"(d[1]), "=r"(d[2]), "=r"(d[3]) : "r"(a));
}
__device__ __forceinline__ void cp16(void* smp, const void* gp) {
    unsigned sa = (unsigned)__cvta_generic_to_shared(smp);
    asm volatile("cp.async.cg.shared.global [%0], [%1], 16;\n" :: "r"(sa), "l"(gp));
}
__device__ __forceinline__ unsigned shaddr(const void* p) {
    return (unsigned)__cvta_generic_to_shared(p);
}

// ---------------- LayerNorm -> bf16 hi/lo planes ----------------
__global__ void ln_kernel(const float* __restrict__ x,
                          const float* __restrict__ gw,
                          const float* __restrict__ bw,
                          bf16* __restrict__ oh, bf16* __restrict__ ol) {
    int row = blockIdx.x;
    const float* xr = x + (size_t)row * DIM_;
    int t = threadIdx.x;
    int c = t * 4;

    float4 v = *(const float4*)(xr + c);
    float s = v.x + v.y + v.z + v.w;
    float sq = v.x * v.x + v.y * v.y + v.z * v.z + v.w * v.w;
    __shared__ float sh[64];
#pragma unroll
    for (int o = 16; o > 0; o >>= 1) {
        s  += __shfl_down_sync(0xffffffffu, s,  o);
        sq += __shfl_down_sync(0xffffffffu, sq, o);
    }
    if ((t & 31) == 0) { sh[t >> 5] = s; sh[32 + (t >> 5)] = sq; }
    __syncthreads();
    if (t < 32) {
        float a  = (t < 8) ? sh[t]      : 0.f;
        float b2 = (t < 8) ? sh[32 + t] : 0.f;
#pragma unroll
        for (int o = 4; o > 0; o >>= 1) {
            a  += __shfl_down_sync(0xffffffffu, a,  o);
            b2 += __shfl_down_sync(0xffffffffu, b2, o);
        }
        if (t == 0) { sh[0] = a; sh[1] = b2; }
    }
    __syncthreads();
    float mu   = sh[0] * (1.f / DIM_);
    float var  = sh[1] * (1.f / DIM_) - mu * mu;
    float rstd = rsqrtf(var + EPS_);
    float y0 = (v.x - mu) * rstd * gw[c + 0] + bw[c + 0];
    float y1 = (v.y - mu) * rstd * gw[c + 1] + bw[c + 1];
    float y2 = (v.z - mu) * rstd * gw[c + 2] + bw[c + 2];
    float y3 = (v.w - mu) * rstd * gw[c + 3] + bw[c + 3];
    size_t o0 = (size_t)row * DIM_ + c;
    unsigned lo, hi;
    hi = packsplit(y0, y1, lo);
    *(unsigned*)&oh[o0] = hi; *(unsigned*)&ol[o0] = lo;
    hi = packsplit(y2, y3, lo);
    *(unsigned*)&oh[o0 + 2] = hi; *(unsigned*)&ol[o0 + 2] = lo;
}

// ---------------- all 6 weights fp32 -> bf16 hi/lo, single launch ---------
__global__ void wconv_all(const float* __restrict__ w0, const float* __restrict__ w1,
                          const float* __restrict__ w2, const float* __restrict__ w3,
                          const float* __restrict__ w4, const float* __restrict__ w5,
                          bf16* __restrict__ Wh, bf16* __restrict__ Wl) {
    const float* srcs[6] = {w0, w1, w2, w3, w4, w5};
    int w = blockIdx.y;
    const float* W = srcs[w];
    size_t base = (size_t)w * DIM_ * INNER_;
    size_t i = ((size_t)blockIdx.x * 256 + threadIdx.x) * 2;
    float2 v = *(const float2*)(W + i);
    unsigned lo, hi = packsplit(v.x, v.y, lo);
    *(unsigned*)&Wh[base + i] = hi;
    *(unsigned*)&Wl[base + i] = lo;
}

// ================= hi/lo split tensor-core GEMM (2-stage cp.async) ========
// DT: bf16 or half.  A: ATR ? [K][M] : [M][K].  B: BKN ? [K][N] : [N][K].
// APL: # of A planes.  OMODE: 0 fp32+bias; 1 bf16 planes; 2 exp->fp16 sim +
// softmax stat partials; 3 fp16 planes.
// MMA issue is TERM-MAJOR: same-accumulator revisit spacing of 4 issues to
// hide HMMA accumulator RAW latency.
template <class DT, int BN, bool ATR, bool BKN, int APL, int OMODE>
__device__ __forceinline__ void tgemm(const DT* __restrict__ Ah,
                                      const DT* __restrict__ Al, int lda,
                                      const DT* __restrict__ Bh,
                                      const DT* __restrict__ Bl, int ldb,
                                      float* __restrict__ C,
                                      bf16* __restrict__ Ch,
                                      bf16* __restrict__ Cl,
                                      half* __restrict__ Fh,
                                      half* __restrict__ Fl,
                                      int ldc, int K,
                                      const float* __restrict__ bias,
                                      float alpha) {
    constexpr int BM = 128, BK = 32;
    constexpr int SAS = ATR ? (BM + 8) : (BK + 8);
    constexpr int SBS = BKN ? (BN + 8) : (BK + 8);
    constexpr int ASZ = (ATR ? BK : BM) * SAS;
    constexpr int BSZ = (BKN ? BK : BN) * SBS;
    constexpr int NT8 = BN / 16;
    constexpr int NG  = BN / 32;
    constexpr int CB  = BN * 4;

    extern __shared__ unsigned char smraw[];
    DT* sm = (DT*)smraw;
    const int t = threadIdx.x, lane = t & 31, warp = t >> 5;
    const int gi = lane >> 2, gj = lane & 3;
    const int wm = (warp >> 1) * 32, wn = (warp & 1) * (BN / 2);
    const int m0 = blockIdx.y * BM, n0 = blockIdx.x * BN;

    float acc[2][NT8][4];
#pragma unroll
    for (int a = 0; a < 2; a++)
#pragma unroll
        for (int b = 0; b < NT8; b++)
#pragma unroll
            for (int q = 0; q < 4; q++) acc[a][b][q] = 0.f;

    auto cpA = [&](int kc, int bufi) {
#pragma unroll
        for (int p = 0; p < APL; p++) {
            const DT* src = p ? Al : Ah;
            DT* dst = sm + p * 2 * ASZ + bufi * ASZ;
            if (!ATR) {
#pragma unroll
                for (int q = t; q < 512; q += 256) {
                    int row = q >> 2, c = (q & 3) * 8;
                    cp16(dst + row * SAS + c,
                         src + (size_t)(m0 + row) * lda + kc * BK + c);
                }
            } else {
#pragma unroll
                for (int q = t; q < 512; q += 256) {
                    int row = q >> 4, c = (q & 15) * 8;
                    cp16(dst + row * SAS + c,
                         src + (size_t)(kc * BK + row) * lda + m0 + c);
                }
            }
        }
    };
    auto cpB = [&](int kc, int bufi) {
#pragma unroll
        for (int p = 0; p < 2; p++) {
            const DT* src = p ? Bl : Bh;
            DT* dst = sm + APL * 2 * ASZ + p * 2 * BSZ + bufi * BSZ;
            if (BKN) {
#pragma unroll
                for (int q = t; q < CB; q += 256) {
                    int row = q / (BN / 8), c = (q % (BN / 8)) * 8;
                    cp16(dst + row * SBS + c,
                         src + (size_t)(kc * BK + row) * ldb + n0 + c);
                }
            } else {
#pragma unroll
                for (int q = t; q < CB; q += 256) {
                    int row = q >> 2, c = (q & 3) * 8;
                    cp16(dst + row * SBS + c,
                         src + (size_t)(n0 + row) * ldb + kc * BK + c);
                }
            }
        }
    };

    const int NK = K / BK;
    cpA(0, 0); cpB(0, 0);
    asm volatile("cp.async.commit_group;\n");
    int buf = 0;

    for (int kc = 0; kc < NK; kc++) {
        if (kc + 1 < NK) {
            cpA(kc + 1, buf ^ 1); cpB(kc + 1, buf ^ 1);
            asm volatile("cp.async.commit_group;\n");
            asm volatile("cp.async.wait_group 1;\n");
        } else {
            asm volatile("cp.async.wait_group 0;\n");
        }
        __syncthreads();

        const DT* sAh = sm + buf * ASZ;
        const DT* sAl = sm + 2 * ASZ + buf * ASZ;
        const DT* sBh = sm + APL * 2 * ASZ + buf * BSZ;
        const DT* sBl = sm + APL * 2 * ASZ + 2 * BSZ + buf * BSZ;

#pragma unroll
        for (int ks = 0; ks < 2; ks++) {
            const int kofs = ks * 16;
            unsigned aH[2][4], aL[2][4];
            if (!ATR) {
                int r = lane & 15, c = (lane >> 4) * 8;
#pragma unroll
                for (int mt = 0; mt < 2; mt++) {
                    int off = (wm + mt * 16 + r) * SAS + kofs + c;
                    ldsm4(aH[mt], shaddr(sAh + off));
                    if (APL == 2) ldsm4(aL[mt], shaddr(sAl + off));
                }
            } else {
                int kr = kofs + (lane & 7) + ((lane >> 4) << 3);
#pragma unroll
                for (int mt = 0; mt < 2; mt++) {
                    int mc = wm + mt * 16 + (lane & 8);
                    int off = kr * SAS + mc;
                    ldsm4t(aH[mt], shaddr(sAh + off));
                    if (APL == 2) ldsm4t(aL[mt], shaddr(sAl + off));
                }
            }
#pragma unroll
            for (int g = 0; g < NG; g++) {
                unsigned bH[4], bL[4];
                int nb = wn + g * 16;
                if (BKN) {
                    int kr = kofs + (lane & 7) + ((lane & 8) ? 8 : 0);
                    int nc = nb + ((lane & 16) ? 8 : 0);
                    int off = kr * SBS + nc;
                    ldsm4t(bH, shaddr(sBh + off));
                    ldsm4t(bL, shaddr(sBl + off));
                } else {
                    int nr = nb + (lane & 7) + ((lane & 16) ? 8 : 0);
                    int kc2 = kofs + ((lane & 8) ? 8 : 0);
                    int off = nr * SBS + kc2;
                    ldsm4(bH, shaddr(sBh + off));
                    ldsm4(bL, shaddr(sBl + off));
                }
                // term-major issue: HH x4, HL x4, LH x4 -> acc revisit gap = 4
#pragma unroll
                for (int mt = 0; mt < 2; mt++) {
                    Mma<DT>::op(acc[mt][2 * g],     aH[mt], bH);
                    Mma<DT>::op(acc[mt][2 * g + 1], aH[mt], bH + 2);
                }
#pragma unroll
                for (int mt = 0; mt < 2; mt++) {
                    Mma<DT>::op(acc[mt][2 * g],     aH[mt], bL);
                    Mma<DT>::op(acc[mt][2 * g + 1], aH[mt], bL + 2);
                }
                if (APL == 2) {
#pragma unroll
                    for (int mt = 0; mt < 2; mt++) {
                        Mma<DT>::op(acc[mt][2 * g],     aL[mt], bH);
                        Mma<DT>::op(acc[mt][2 * g + 1], aL[mt], bH + 2);
                    }
                }
            }
        }
        __syncthreads();
        buf ^= 1;
    }

    if constexpr (OMODE == 2) {
        // exp -> fp16 sim (smem-staged coalesced store) + softmax partials
        __shared__ float rsm[2][128];
        __shared__ float csm[4][128];
        constexpr int SCS = 136;                  // half stride, conflict-free
        half* sc = (half*)smraw;                  // 128*136*2 = 34816 B, fits
        float rsum[2][2] = {};
        float csum[NT8][2] = {};
#pragma unroll
        for (int mt = 0; mt < 2; mt++)
#pragma unroll
            for (int nt = 0; nt < NT8; nt++) {
                int r = wm + mt * 16 + gi;
                int c = wn + nt * 8 + 2 * gj;
                float e0 = __expf(acc[mt][nt][0] * alpha);
                float e1 = __expf(acc[mt][nt][1] * alpha);
                float e2 = __expf(acc[mt][nt][2] * alpha);
                float e3 = __expf(acc[mt][nt][3] * alpha);
                *(half2*)&sc[r * SCS + c]       = __floats2half2_rn(e0, e1);
                *(half2*)&sc[(r + 8) * SCS + c] = __floats2half2_rn(e2, e3);
                rsum[mt][0] += e0 + e1;
                rsum[mt][1] += e2 + e3;
                csum[nt][0] += e0 + e2;
                csum[nt][1] += e1 + e3;
            }
#pragma unroll
        for (int mt = 0; mt < 2; mt++)
#pragma unroll
            for (int rh = 0; rh < 2; rh++) {
                float v = rsum[mt][rh];
                v += __shfl_xor_sync(0xffffffffu, v, 1);
                v += __shfl_xor_sync(0xffffffffu, v, 2);
                if (gj == 0) rsm[warp & 1][wm + mt * 16 + gi + rh * 8] = v;
            }
#pragma unroll
        for (int nt = 0; nt < NT8; nt++)
#pragma unroll
            for (int q = 0; q < 2; q++) {
                float v = csum[nt][q];
                v += __shfl_xor_sync(0xffffffffu, v, 4);
                v += __shfl_xor_sync(0xffffffffu, v, 8);
                v += __shfl_xor_sync(0xffffffffu, v, 16);
                if (gi == 0) csm[warp >> 1][wn + nt * 8 + 2 * gj + q] = v;
            }
        __syncthreads();
        // coalesced flush: 128 rows x 128 halves = 128 x 16 chunks of 16B
#pragma unroll
        for (int it = 0; it < 8; it++) {
            int row = (t >> 4) + it * 16;
            int ch = t & 15;
            uint4 vv = *(uint4*)&sc[row * SCS + ch * 8];
            *(uint4*)&Fh[(size_t)(m0 + row) * ldc + n0 + ch * 8] = vv;
        }
        if (t < 128) {
            float rtot = rsm[0][t] + rsm[1][t];
            g_rp[((size_t)blockIdx.z * I_ + m0 + t) * 16 + blockIdx.x] = rtot;
            float ctot = csm[0][t] + csm[1][t] + csm[2][t] + csm[3][t];
            g_cp[((size_t)blockIdx.z * J_ + n0 + t) * 16 + blockIdx.y] = ctot;
        }
        return;
    }

#pragma unroll
    for (int mt = 0; mt < 2; mt++)
#pragma unroll
        for (int nt = 0; nt < NT8; nt++) {
            int r = m0 + wm + mt * 16 + gi;
            int c = n0 + wn + nt * 8 + 2 * gj;
            const float* a = acc[mt][nt];
            if constexpr (OMODE == 0) {
                float b0 = bias ? bias[c] : 0.f;
                float b1 = bias ? bias[c + 1] : 0.f;
                float2 v0 = {a[0] * alpha + b0, a[1] * alpha + b1};
                float2 v1 = {a[2] * alpha + b0, a[3] * alpha + b1};
                *(float2*)&C[(size_t)r * ldc + c] = v0;
                *(float2*)&C[(size_t)(r + 8) * ldc + c] = v1;
            } else if constexpr (OMODE == 1) {
                unsigned lo, hi;
                hi = packsplit(a[0], a[1], lo);
                *(unsigned*)&Ch[(size_t)r * ldc + c] = hi;
                *(unsigned*)&Cl[(size_t)r * ldc + c] = lo;
                hi = packsplit(a[2], a[3], lo);
                *(unsigned*)&Ch[(size_t)(r + 8) * ldc + c] = hi;
                *(unsigned*)&Cl[(size_t)(r + 8) * ldc + c] = lo;
            } else {   // OMODE == 3
                unsigned lo, hi;
                hi = packsplit_h(a[0], a[1], lo);
                *(unsigned*)&Fh[(size_t)r * ldc + c] = hi;
                *(unsigned*)&Fl[(size_t)r * ldc + c] = lo;
                hi = packsplit_h(a[2], a[3], lo);
                *(unsigned*)&Fh[(size_t)(r + 8) * ldc + c] = hi;
                *(unsigned*)&Fl[(size_t)(r + 8) * ldc + c] = lo;
            }
        }
}

// ---- kernel wrappers (all capped for 2 CTAs/SM) ----
// all 4 input projections in ONE launch; z selects {Q, ctxQ, V, ctxV}
__global__ void __launch_bounds__(256, 2) k_proj4() {
    int z = blockIdx.z;
    if (z == 0) {
        tgemm<bf16, 128, false, true, 2, 1>(g_xnh, g_xnl, DIM_,
                                            g_wh[0], g_wl[0], INNER_,
                                            nullptr, g_qkh, g_qkl, nullptr,
                                            nullptr, INNER_, DIM_, nullptr, 1.f);
    } else if (z == 1) {
        tgemm<bf16, 128, false, true, 2, 1>(g_cnh, g_cnl, DIM_,
                                            g_wh[1], g_wl[1], INNER_,
                                            nullptr, g_ckh, g_ckl, nullptr,
                                            nullptr, INNER_, DIM_, nullptr, 1.f);
    } else if (z == 2) {
        tgemm<bf16, 128, false, true, 2, 3>(g_xnh, g_xnl, DIM_,
                                            g_wh[2], g_wl[2], INNER_,
                                            nullptr, nullptr, nullptr,
                                            g_vh, g_vl, INNER_, DIM_, nullptr, 1.f);
    } else {
        tgemm<bf16, 128, false, true, 2, 3>(g_cnh, g_cnl, DIM_,
                                            g_wh[3], g_wl[3], INNER_,
                                            nullptr, nullptr, nullptr,
                                            g_cvh, g_cvl, INNER_, DIM_, nullptr, 1.f);
    }
}
// both output projections in ONE launch
__global__ void __launch_bounds__(256, 2) k_projF2(float* out,
                                                   const float* b_out,
                                                   const float* b_cout) {
    if (blockIdx.z == 0) {
        tgemm<bf16, 128, false, true, 2, 0>(g_o1h, g_o1l, INNER_,
                                            g_wh[4], g_wl[4], DIM_,
                                            out, nullptr, nullptr, nullptr,
                                            nullptr, DIM_, INNER_, b_out, 1.f);
    } else {
        tgemm<bf16, 128, false, true, 2, 0>(g_o2h, g_o2l, INNER_,
                                            g_wh[5], g_wl[5], DIM_,
                                            out + (size_t)B_ * I_ * DIM_,
                                            nullptr, nullptr, nullptr,
                                            nullptr, DIM_, INNER_, b_cout, 1.f);
    }
}
// sim: exp(scale*QK) -> fp16 + softmax stat partials
__global__ void __launch_bounds__(256, 2) k_sim() {
    int z = blockIdx.z, b = z >> 4, h = z & 15;
    size_t qo = (size_t)b * I_ * INNER_ + h * DH_;
    size_t ko = (size_t)b * J_ * INNER_ + h * DH_;
    tgemm<bf16, 128, false, false, 2, 2>(g_qkh + qo, g_qkl + qo, INNER_,
                                         g_ckh + ko, g_ckl + ko, INNER_,
                                         nullptr, nullptr, nullptr,
                                         g_sim16 + (size_t)z * I_ * J_, nullptr,
                                         J_, DH_, nullptr, SCALE_);
}
// both AV GEMMs in ONE launch: z<NZ_ -> attn@ctx_v, else cattn^T@v
__global__ void __launch_bounds__(256, 2) k_avx() {
    int z = blockIdx.z;
    if (z < NZ_) {
        int b = z >> 4, h = z & 15;
        size_t ao = (size_t)z * I_ * J_;
        size_t vo = (size_t)b * J_ * INNER_ + h * DH_;
        size_t oo = (size_t)b * I_ * INNER_ + h * DH_;
        tgemm<half, 64, false, true, 1, 1>(g_at16 + ao, nullptr, J_,
                                           g_cvh + vo, g_cvl + vo, INNER_,
                                           nullptr, g_o1h + oo, g_o1l + oo,
                                           nullptr, nullptr, INNER_, J_,
                                           nullptr, 1.f);
    } else {
        int zz = z - NZ_;
        int b = zz >> 4, h = zz & 15;
        size_t ao = (size_t)zz * I_ * J_;
        size_t vo = (size_t)b * I_ * INNER_ + h * DH_;
        size_t oo = (size_t)b * J_ * INNER_ + h * DH_;
        tgemm<half, 64, true, true, 1, 1>(g_ct16 + ao, nullptr, J_,
                                          g_vh + vo, g_vl + vo, INNER_,
                                          nullptr, g_o2h + oo, g_o2l + oo,
                                          nullptr, nullptr, INNER_, I_,
                                          nullptr, 1.f);
    }
}

// ---------------- stat partial reduction: 1/sum ----------------
__global__ void statreduce() {
    int idx = blockIdx.x * 256 + threadIdx.x;
    const float* src = blockIdx.y ? g_cp : g_rp;
    const float4* s4 = (const float4*)(src + (size_t)idx * 16);
    float4 a = s4[0], b = s4[1], c = s4[2], d = s4[3];
    float s = a.x + a.y + a.z + a.w + b.x + b.y + b.z + b.w
            + c.x + c.y + c.z + c.w + d.x + d.y + d.z + d.w;
    (blockIdx.y ? g_cs : g_rs)[idx] = 1.f / s;
}

// ------- fused softmax-normalize + talking-heads mix, 2 j per thread ------
__global__ void mix_kernel(const float* __restrict__ thw,
                           const float* __restrict__ cthw) {
    int b = blockIdx.z;
    int i = blockIdx.y;
    int t = threadIdx.x;
    int j = (blockIdx.x * 256 + t) * 2;

    __shared__ float wR[16][16], wC[16][16], ri[16];
    wR[t >> 4][t & 15] = thw[t];
    wC[t >> 4][t & 15] = cthw[t];
    if (t < 16) ri[t] = g_rs[((size_t)(b * H_ + t)) * I_ + i];
    __syncthreads();

    float2 pr[16], pc[16];
#pragma unroll
    for (int h = 0; h < 16; h++) {
        size_t zi = (size_t)(b * H_ + h);
        half2 e2 = *(const half2*)&g_sim16[(zi * I_ + i) * J_ + j];
        float2 e = __half22float2(e2);
        float rih = ri[h];
        float2 cv = *(const float2*)&g_cs[zi * J_ + j];
        pr[h].x = e.x * rih;   pr[h].y = e.y * rih;
        pc[h].x = e.x * cv.x;  pc[h].y = e.y * cv.y;
    }
#pragma unroll
    for (int g = 0; g < 16; g++) {
        float aR0 = 0.f, aR1 = 0.f, aC0 = 0.f, aC1 = 0.f;
#pragma unroll
        for (int h = 0; h < 16; h++) {
            float wr = wR[g][h], wc = wC[g][h];
            aR0 += wr * pr[h].x; aR1 += wr * pr[h].y;
            aC0 += wc * pc[h].x; aC1 += wc * pc[h].y;
        }
        size_t idx = (((size_t)(b * H_ + g)) * I_ + i) * J_ + j;
        *(half2*)&g_at16[idx] = __floats2half2_rn(aR0, aR1);
        *(half2*)&g_ct16[idx] = __floats2half2_rn(aC0, aC1);
    }
}

// ---------------- launch ----------------
extern "C" void kernel_launch(void* const* d_in, const int* in_sizes, int n_in,
                              void* d_out, int out_size) {
    const float* x     = (const float*)d_in[0];
    const float* ctx   = (const float*)d_in[1];
    const float* ln_g  = (const float*)d_in[2];
    const float* ln_b  = (const float*)d_in[3];
    const float* cln_g = (const float*)d_in[4];
    const float* cln_b = (const float*)d_in[5];
    const float* W_qk  = (const float*)d_in[6];
    const float* W_cqk = (const float*)d_in[7];
    const float* W_v   = (const float*)d_in[8];
    const float* W_cv  = (const float*)d_in[9];
    const float* W_out = (const float*)d_in[10];
    const float* b_out = (const float*)d_in[11];
    const float* W_cout= (const float*)d_in[12];
    const float* b_cout= (const float*)d_in[13];
    const float* thw   = (const float*)d_in[14];
    const float* cthw  = (const float*)d_in[15];
    float* out = (float*)d_out;

    bf16 *xnh, *xnl, *cnh, *cnl, *wh, *wl;
    cudaGetSymbolAddress((void**)&xnh, g_xnh); cudaGetSymbolAddress((void**)&xnl, g_xnl);
    cudaGetSymbolAddress((void**)&cnh, g_cnh); cudaGetSymbolAddress((void**)&cnl, g_cnl);
    cudaGetSymbolAddress((void**)&wh,  g_wh);  cudaGetSymbolAddress((void**)&wl,  g_wl);

    // smem sizes (bytes) for 2-stage GEMMs
    constexpr int SM_PROJ = (2 * 2 * 128 * 40 + 2 * 2 * 32 * 136) * 2;  // 75776
    constexpr int SM_SIM  = (2 * 2 * 128 * 40 + 2 * 2 * 128 * 40) * 2;  // 81920
    constexpr int SM_AVX  = (1 * 2 * 128 * 40 + 2 * 2 * 32 * 72) * 2;   // 38912
    cudaFuncSetAttribute(k_proj4,  cudaFuncAttributeMaxDynamicSharedMemorySize, SM_PROJ);
    cudaFuncSetAttribute(k_projF2, cudaFuncAttributeMaxDynamicSharedMemorySize, SM_PROJ);
    cudaFuncSetAttribute(k_sim,    cudaFuncAttributeMaxDynamicSharedMemorySize, SM_SIM);
    cudaFuncSetAttribute(k_avx,    cudaFuncAttributeMaxDynamicSharedMemorySize, SM_AVX);

    // 1) layernorms + weight conversion
    ln_kernel<<<B_ * I_, 256>>>(x,   ln_g,  ln_b,  xnh, xnl);
    ln_kernel<<<B_ * J_, 256>>>(ctx, cln_g, cln_b, cnh, cnl);
    wconv_all<<<dim3(2048, 6), 256>>>(W_qk, W_cqk, W_v, W_cv, W_out, W_cout, wh, wl);

    // 2) all 4 input projections, single launch
    k_proj4<<<dim3(DIM_ / 128, (B_ * I_) / 128, 4), 256, SM_PROJ>>>();

    // 3) sim -> exp (fp16) + softmax stat partials
    k_sim<<<dim3(J_ / 128, I_ / 128, NZ_), 256, SM_SIM>>>();

    // 4) reduce partials -> 1/rowsum, 1/colsum
    statreduce<<<dim3(NZ_ * I_ / 256, 2), 256>>>();

    // 5) normalize + talking-heads mix -> fp16 attn planes
    mix_kernel<<<dim3(J_ / 512, I_, B_), 256>>>(thw, cthw);

    // 6) both attention-weighted-value GEMM families, single launch
    k_avx<<<dim3(1, I_ / 128, 2 * NZ_), 256, SM_AVX>>>();

    // 7) both output projections, single launch
    k_projF2<<<dim3(DIM_ / 128, (B_ * I_) / 128, 2), 256, SM_PROJ>>>(out, b_out, b_cout);
}

// round 13
// speedup vs baseline: 1.0109x; 1.0109x over previous
#include <cuda_runtime.h>
#include <cuda_bf16.h>
#include <cuda_fp16.h>
#include <math.h>

typedef __nv_bfloat16 bf16;

// ---------------- problem constants ----------------
#define B_     2
#define I_     2048
#define J_     2048
#define DIM_   1024
#define H_     16
#define DH_    64
#define INNER_ 1024
#define EPS_   1e-5f
#define SCALE_ 0.125f   // DH^-0.5
#define SIMN   134217728   // B*H*I*J
#define NZ_    32          // B*H

// ---------------- scratch (device globals; allocation-free) ----------------
__device__ bf16 g_xnh[B_ * I_ * DIM_],  g_xnl[B_ * I_ * DIM_];
__device__ bf16 g_cnh[B_ * J_ * DIM_],  g_cnl[B_ * J_ * DIM_];
__device__ bf16 g_qkh[B_ * I_ * INNER_], g_qkl[B_ * I_ * INNER_];
__device__ bf16 g_ckh[B_ * J_ * INNER_], g_ckl[B_ * J_ * INNER_];
__device__ half g_vh [B_ * I_ * INNER_], g_vl [B_ * I_ * INNER_];
__device__ half g_cvh[B_ * J_ * INNER_], g_cvl[B_ * J_ * INNER_];
__device__ bf16 g_o1h[B_ * I_ * INNER_], g_o1l[B_ * I_ * INNER_];
__device__ bf16 g_o2h[B_ * J_ * INNER_], g_o2l[B_ * J_ * INNER_];
__device__ bf16 g_wh[6][DIM_ * INNER_], g_wl[6][DIM_ * INNER_];
__device__ half g_sim16[SIMN];                // exp(scale*QK) fp16, 256 MB
__device__ half g_at16[SIMN], g_ct16[SIMN];   // mixed attn, fp16
__device__ float g_rp[NZ_ * I_ * 16], g_cp[NZ_ * J_ * 16];  // tile partial sums
__device__ float g_rs[NZ_ * I_], g_cs[NZ_ * J_];            // 1/rowsum, 1/colsum

// ---------------- helpers ----------------
__device__ __forceinline__ unsigned packsplit(float x, float y, unsigned& lo) {
    bf16 hx = __float2bfloat16(x);
    bf16 hy = __float2bfloat16(y);
    float lx = x - __bfloat162float(hx);
    float ly = y - __bfloat162float(hy);
    __nv_bfloat162 l2 = __floats2bfloat162_rn(lx, ly);
    lo = *(unsigned*)&l2;
    __nv_bfloat162 h2 = __halves2bfloat162(hx, hy);
    return *(unsigned*)&h2;
}
__device__ __forceinline__ unsigned packsplit_h(float x, float y, unsigned& lo) {
    half hx = __float2half(x);
    half hy = __float2half(y);
    float lx = x - __half2float(hx);
    float ly = y - __half2float(hy);
    half2 l2 = __floats2half2_rn(lx, ly);
    lo = *(unsigned*)&l2;
    half2 h2 = __halves2half2(hx, hy);
    return *(unsigned*)&h2;
}
template <class T> struct Mma;
template <> struct Mma<bf16> {
    static __device__ __forceinline__ void op(float* c, const unsigned* a,
                                              const unsigned* b) {
        asm volatile(
            "mma.sync.aligned.m16n8k16.row.col.f32.bf16.bf16.f32 "
            "{%0,%1,%2,%3}, {%4,%5,%6,%7}, {%8,%9}, {%0,%1,%2,%3};\n"
            : "+f"(c[0]), "+f"(c[1]), "+f"(c[2]), "+f"(c[3])
            : "r"(a[0]), "r"(a[1]), "r"(a[2]), "r"(a[3]), "r"(b[0]), "r"(b[1]));
    }
};
template <> struct Mma<half> {
    static __device__ __forceinline__ void op(float* c, const unsigned* a,
                                              const unsigned* b) {
        asm volatile(
            "mma.sync.aligned.m16n8k16.row.col.f32.f16.f16.f32 "
            "{%0,%1,%2,%3}, {%4,%5,%6,%7}, {%8,%9}, {%0,%1,%2,%3};\n"
            : "+f"(c[0]), "+f"(c[1]), "+f"(c[2]), "+f"(c[3])
            : "r"(a[0]), "r"(a[1]), "r"(a[2]), "r"(a[3]), "r"(b[0]), "r"(b[1]));
    }
};
__device__ __forceinline__ void ldsm4(unsigned* d, unsigned a) {
    asm volatile("ldmatrix.sync.aligned.m8n8.x4.shared.b16 {%0,%1,%2,%3},[%4];\n"
                 : "=r"(d[0]), "=r"(d[1]), "=r"(d[2]), "=r"(d[3]) : "r"(a));
}
__device__ __forceinline__ void ldsm4t(unsigned* d, unsigned a) {
    asm volatile("ldmatrix.sync.aligned.m8n8.x4.trans.shared.b16 {%0,%1,%2,%3},[%4];\n"
                 : "=r"(d[0]), "=r"(d[1]), "=r"(d[2]), "=r"(d[3]) : "r"(a));
}
__device__ __forceinline__ void cp16(void* smp, const void* gp) {
    unsigned sa = (unsigned)__cvta_generic_to_shared(smp);
    asm volatile("cp.async.cg.shared.global [%0], [%1], 16;\n" :: "r"(sa), "l"(gp));
}
__device__ __forceinline__ unsigned shaddr(const void* p) {
    return (unsigned)__cvta_generic_to_shared(p);
}

// ---------------- LayerNorm -> bf16 hi/lo planes ----------------
__global__ void ln_kernel(const float* __restrict__ x,
                          const float* __restrict__ gw,
                          const float* __restrict__ bw,
                          bf16* __restrict__ oh, bf16* __restrict__ ol) {
    int row = blockIdx.x;
    const float* xr = x + (size_t)row * DIM_;
    int t = threadIdx.x;
    int c = t * 4;

    float4 v = *(const float4*)(xr + c);
    float s = v.x + v.y + v.z + v.w;
    float sq = v.x * v.x + v.y * v.y + v.z * v.z + v.w * v.w;
    __shared__ float sh[64];
#pragma unroll
    for (int o = 16; o > 0; o >>= 1) {
        s  += __shfl_down_sync(0xffffffffu, s,  o);
        sq += __shfl_down_sync(0xffffffffu, sq, o);
    }
    if ((t & 31) == 0) { sh[t >> 5] = s; sh[32 + (t >> 5)] = sq; }
    __syncthreads();
    if (t < 32) {
        float a  = (t < 8) ? sh[t]      : 0.f;
        float b2 = (t < 8) ? sh[32 + t] : 0.f;
#pragma unroll
        for (int o = 4; o > 0; o >>= 1) {
            a  += __shfl_down_sync(0xffffffffu, a,  o);
            b2 += __shfl_down_sync(0xffffffffu, b2, o);
        }
        if (t == 0) { sh[0] = a; sh[1] = b2; }
    }
    __syncthreads();
    float mu   = sh[0] * (1.f / DIM_);
    float var  = sh[1] * (1.f / DIM_) - mu * mu;
    float rstd = rsqrtf(var + EPS_);
    float y0 = (v.x - mu) * rstd * gw[c + 0] + bw[c + 0];
    float y1 = (v.y - mu) * rstd * gw[c + 1] + bw[c + 1];
    float y2 = (v.z - mu) * rstd * gw[c + 2] + bw[c + 2];
    float y3 = (v.w - mu) * rstd * gw[c + 3] + bw[c + 3];
    size_t o0 = (size_t)row * DIM_ + c;
    unsigned lo, hi;
    hi = packsplit(y0, y1, lo);
    *(unsigned*)&oh[o0] = hi; *(unsigned*)&ol[o0] = lo;
    hi = packsplit(y2, y3, lo);
    *(unsigned*)&oh[o0 + 2] = hi; *(unsigned*)&ol[o0 + 2] = lo;
}

// ---------------- all 6 weights fp32 -> bf16 hi/lo, single launch ---------
__global__ void wconv_all(const float* __restrict__ w0, const float* __restrict__ w1,
                          const float* __restrict__ w2, const float* __restrict__ w3,
                          const float* __restrict__ w4, const float* __restrict__ w5,
                          bf16* __restrict__ Wh, bf16* __restrict__ Wl) {
    const float* srcs[6] = {w0, w1, w2, w3, w4, w5};
    int w = blockIdx.y;
    const float* W = srcs[w];
    size_t base = (size_t)w * DIM_ * INNER_;
    size_t i = ((size_t)blockIdx.x * 256 + threadIdx.x) * 2;
    float2 v = *(const float2*)(W + i);
    unsigned lo, hi = packsplit(v.x, v.y, lo);
    *(unsigned*)&Wh[base + i] = hi;
    *(unsigned*)&Wl[base + i] = lo;
}

// ================= hi/lo split tensor-core GEMM (NSTAGE-deep cp.async) ====
// DT: bf16 or half.  A: ATR ? [K][M] : [M][K].  B: BKN ? [K][N] : [N][K].
// APL: # of A planes.  OMODE: 0 fp32+bias; 1 bf16 planes; 2 exp->fp16 sim +
// softmax stat partials; 3 fp16 planes.
template <class DT, int BN, bool ATR, bool BKN, int APL, int OMODE, int NSTAGE>
__device__ __forceinline__ void tgemm(const DT* __restrict__ Ah,
                                      const DT* __restrict__ Al, int lda,
                                      const DT* __restrict__ Bh,
                                      const DT* __restrict__ Bl, int ldb,
                                      float* __restrict__ C,
                                      bf16* __restrict__ Ch,
                                      bf16* __restrict__ Cl,
                                      half* __restrict__ Fh,
                                      half* __restrict__ Fl,
                                      int ldc, int K,
                                      const float* __restrict__ bias,
                                      float alpha) {
    constexpr int BM = 128, BK = 32;
    constexpr int SAS = ATR ? (BM + 8) : (BK + 8);
    constexpr int SBS = BKN ? (BN + 8) : (BK + 8);
    constexpr int ASZ = (ATR ? BK : BM) * SAS;
    constexpr int BSZ = (BKN ? BK : BN) * SBS;
    constexpr int NT8 = BN / 16;
    constexpr int NG  = BN / 32;
    constexpr int CB  = BN * 4;

    extern __shared__ unsigned char smraw[];
    DT* sm = (DT*)smraw;
    const int t = threadIdx.x, lane = t & 31, warp = t >> 5;
    const int gi = lane >> 2, gj = lane & 3;
    const int wm = (warp >> 1) * 32, wn = (warp & 1) * (BN / 2);
    const int m0 = blockIdx.y * BM, n0 = blockIdx.x * BN;

    float acc[2][NT8][4];
#pragma unroll
    for (int a = 0; a < 2; a++)
#pragma unroll
        for (int b = 0; b < NT8; b++)
#pragma unroll
            for (int q = 0; q < 4; q++) acc[a][b][q] = 0.f;

    auto cpA = [&](int kc, int st) {
#pragma unroll
        for (int p = 0; p < APL; p++) {
            const DT* src = p ? Al : Ah;
            DT* dst = sm + (p * NSTAGE + st) * ASZ;
            if (!ATR) {
#pragma unroll
                for (int q = t; q < 512; q += 256) {
                    int row = q >> 2, c = (q & 3) * 8;
                    cp16(dst + row * SAS + c,
                         src + (size_t)(m0 + row) * lda + kc * BK + c);
                }
            } else {
#pragma unroll
                for (int q = t; q < 512; q += 256) {
                    int row = q >> 4, c = (q & 15) * 8;
                    cp16(dst + row * SAS + c,
                         src + (size_t)(kc * BK + row) * lda + m0 + c);
                }
            }
        }
    };
    auto cpB = [&](int kc, int st) {
#pragma unroll
        for (int p = 0; p < 2; p++) {
            const DT* src = p ? Bl : Bh;
            DT* dst = sm + APL * NSTAGE * ASZ + (p * NSTAGE + st) * BSZ;
            if (BKN) {
#pragma unroll
                for (int q = t; q < CB; q += 256) {
                    int row = q / (BN / 8), c = (q % (BN / 8)) * 8;
                    cp16(dst + row * SBS + c,
                         src + (size_t)(kc * BK + row) * ldb + n0 + c);
                }
            } else {
#pragma unroll
                for (int q = t; q < CB; q += 256) {
                    int row = q >> 2, c = (q & 3) * 8;
                    cp16(dst + row * SBS + c,
                         src + (size_t)(n0 + row) * ldb + kc * BK + c);
                }
            }
        }
    };

    const int NK = K / BK;
#pragma unroll
    for (int s = 0; s < NSTAGE - 1; s++) {
        cpA(s, s); cpB(s, s);
        asm volatile("cp.async.commit_group;\n");
    }

    int st = 0, pfst = NSTAGE - 1;
    for (int kc = 0; kc < NK; kc++) {
        int pf = kc + NSTAGE - 1;
        if (pf < NK) {
            cpA(pf, pfst); cpB(pf, pfst);
            asm volatile("cp.async.commit_group;\n");
            asm volatile("cp.async.wait_group %0;\n" :: "n"(NSTAGE - 1));
        } else {
            asm volatile("cp.async.wait_group 0;\n");
        }
        __syncthreads();

        const DT* sAh = sm + st * ASZ;
        const DT* sAl = sm + (NSTAGE + st) * ASZ;
        const DT* sBh = sm + APL * NSTAGE * ASZ + st * BSZ;
        const DT* sBl = sm + APL * NSTAGE * ASZ + (NSTAGE + st) * BSZ;

#pragma unroll
        for (int ks = 0; ks < 2; ks++) {
            const int kofs = ks * 16;
            unsigned aH[2][4], aL[2][4];
            if (!ATR) {
                int r = lane & 15, c = (lane >> 4) * 8;
#pragma unroll
                for (int mt = 0; mt < 2; mt++) {
                    int off = (wm + mt * 16 + r) * SAS + kofs + c;
                    ldsm4(aH[mt], shaddr(sAh + off));
                    if (APL == 2) ldsm4(aL[mt], shaddr(sAl + off));
                }
            } else {
                int kr = kofs + (lane & 7) + ((lane >> 4) << 3);
#pragma unroll
                for (int mt = 0; mt < 2; mt++) {
                    int mc = wm + mt * 16 + (lane & 8);
                    int off = kr * SAS + mc;
                    ldsm4t(aH[mt], shaddr(sAh + off));
                    if (APL == 2) ldsm4t(aL[mt], shaddr(sAl + off));
                }
            }
#pragma unroll
            for (int g = 0; g < NG; g++) {
                unsigned bH[4], bL[4];
                int nb = wn + g * 16;
                if (BKN) {
                    int kr = kofs + (lane & 7) + ((lane & 8) ? 8 : 0);
                    int nc = nb + ((lane & 16) ? 8 : 0);
                    int off = kr * SBS + nc;
                    ldsm4t(bH, shaddr(sBh + off));
                    ldsm4t(bL, shaddr(sBl + off));
                } else {
                    int nr = nb + (lane & 7) + ((lane & 16) ? 8 : 0);
                    int kc2 = kofs + ((lane & 8) ? 8 : 0);
                    int off = nr * SBS + kc2;
                    ldsm4(bH, shaddr(sBh + off));
                    ldsm4(bL, shaddr(sBl + off));
                }
#pragma unroll
                for (int mt = 0; mt < 2; mt++) {
                    Mma<DT>::op(acc[mt][2 * g], aH[mt], bH);
                    Mma<DT>::op(acc[mt][2 * g], aH[mt], bL);
                    if (APL == 2) Mma<DT>::op(acc[mt][2 * g], aL[mt], bH);
                    Mma<DT>::op(acc[mt][2 * g + 1], aH[mt], bH + 2);
                    Mma<DT>::op(acc[mt][2 * g + 1], aH[mt], bL + 2);
                    if (APL == 2) Mma<DT>::op(acc[mt][2 * g + 1], aL[mt], bH + 2);
                }
            }
        }
        __syncthreads();
        st   = (st + 1 == NSTAGE) ? 0 : st + 1;
        pfst = (pfst + 1 == NSTAGE) ? 0 : pfst + 1;
    }

    if constexpr (OMODE == 2) {
        // exp -> fp16 sim (smem-staged coalesced store) + softmax partials
        __shared__ float rsm[2][128];
        __shared__ float csm[4][128];
        constexpr int SCS = 136;                  // half stride, conflict-free
        half* sc = (half*)smraw;                  // 128*136*2 = 34816 B, fits
        float rsum[2][2] = {};
        float csum[NT8][2] = {};
#pragma unroll
        for (int mt = 0; mt < 2; mt++)
#pragma unroll
            for (int nt = 0; nt < NT8; nt++) {
                int r = wm + mt * 16 + gi;
                int c = wn + nt * 8 + 2 * gj;
                float e0 = __expf(acc[mt][nt][0] * alpha);
                float e1 = __expf(acc[mt][nt][1] * alpha);
                float e2 = __expf(acc[mt][nt][2] * alpha);
                float e3 = __expf(acc[mt][nt][3] * alpha);
                *(half2*)&sc[r * SCS + c]       = __floats2half2_rn(e0, e1);
                *(half2*)&sc[(r + 8) * SCS + c] = __floats2half2_rn(e2, e3);
                rsum[mt][0] += e0 + e1;
                rsum[mt][1] += e2 + e3;
                csum[nt][0] += e0 + e2;
                csum[nt][1] += e1 + e3;
            }
#pragma unroll
        for (int mt = 0; mt < 2; mt++)
#pragma unroll
            for (int rh = 0; rh < 2; rh++) {
                float v = rsum[mt][rh];
                v += __shfl_xor_sync(0xffffffffu, v, 1);
                v += __shfl_xor_sync(0xffffffffu, v, 2);
                if (gj == 0) rsm[warp & 1][wm + mt * 16 + gi + rh * 8] = v;
            }
#pragma unroll
        for (int nt = 0; nt < NT8; nt++)
#pragma unroll
            for (int q = 0; q < 2; q++) {
                float v = csum[nt][q];
                v += __shfl_xor_sync(0xffffffffu, v, 4);
                v += __shfl_xor_sync(0xffffffffu, v, 8);
                v += __shfl_xor_sync(0xffffffffu, v, 16);
                if (gi == 0) csm[warp >> 1][wn + nt * 8 + 2 * gj + q] = v;
            }
        __syncthreads();
        // coalesced flush: 128 rows x 128 halves = 128 x 16 chunks of 16B
#pragma unroll
        for (int it = 0; it < 8; it++) {
            int row = (t >> 4) + it * 16;
            int ch = t & 15;
            uint4 vv = *(uint4*)&sc[row * SCS + ch * 8];
            *(uint4*)&Fh[(size_t)(m0 + row) * ldc + n0 + ch * 8] = vv;
        }
        if (t < 128) {
            float rtot = rsm[0][t] + rsm[1][t];
            g_rp[((size_t)blockIdx.z * I_ + m0 + t) * 16 + blockIdx.x] = rtot;
            float ctot = csm[0][t] + csm[1][t] + csm[2][t] + csm[3][t];
            g_cp[((size_t)blockIdx.z * J_ + n0 + t) * 16 + blockIdx.y] = ctot;
        }
        return;
    }

#pragma unroll
    for (int mt = 0; mt < 2; mt++)
#pragma unroll
        for (int nt = 0; nt < NT8; nt++) {
            int r = m0 + wm + mt * 16 + gi;
            int c = n0 + wn + nt * 8 + 2 * gj;
            const float* a = acc[mt][nt];
            if constexpr (OMODE == 0) {
                float b0 = bias ? bias[c] : 0.f;
                float b1 = bias ? bias[c + 1] : 0.f;
                float2 v0 = {a[0] * alpha + b0, a[1] * alpha + b1};
                float2 v1 = {a[2] * alpha + b0, a[3] * alpha + b1};
                *(float2*)&C[(size_t)r * ldc + c] = v0;
                *(float2*)&C[(size_t)(r + 8) * ldc + c] = v1;
            } else if constexpr (OMODE == 1) {
                unsigned lo, hi;
                hi = packsplit(a[0], a[1], lo);
                *(unsigned*)&Ch[(size_t)r * ldc + c] = hi;
                *(unsigned*)&Cl[(size_t)r * ldc + c] = lo;
                hi = packsplit(a[2], a[3], lo);
                *(unsigned*)&Ch[(size_t)(r + 8) * ldc + c] = hi;
                *(unsigned*)&Cl[(size_t)(r + 8) * ldc + c] = lo;
            } else {   // OMODE == 3
                unsigned lo, hi;
                hi = packsplit_h(a[0], a[1], lo);
                *(unsigned*)&Fh[(size_t)r * ldc + c] = hi;
                *(unsigned*)&Fl[(size_t)r * ldc + c] = lo;
                hi = packsplit_h(a[2], a[3], lo);
                *(unsigned*)&Fh[(size_t)(r + 8) * ldc + c] = hi;
                *(unsigned*)&Fl[(size_t)(r + 8) * ldc + c] = lo;
            }
        }
}

// ---- kernel wrappers (all capped for 2 CTAs/SM) ----
// all 4 input projections in ONE launch; z selects {Q, ctxQ, V, ctxV}
__global__ void __launch_bounds__(256, 2) k_proj4() {
    int z = blockIdx.z;
    if (z == 0) {
        tgemm<bf16, 128, false, true, 2, 1, 2>(g_xnh, g_xnl, DIM_,
                                               g_wh[0], g_wl[0], INNER_,
                                               nullptr, g_qkh, g_qkl, nullptr,
                                               nullptr, INNER_, DIM_, nullptr, 1.f);
    } else if (z == 1) {
        tgemm<bf16, 128, false, true, 2, 1, 2>(g_cnh, g_cnl, DIM_,
                                               g_wh[1], g_wl[1], INNER_,
                                               nullptr, g_ckh, g_ckl, nullptr,
                                               nullptr, INNER_, DIM_, nullptr, 1.f);
    } else if (z == 2) {
        tgemm<bf16, 128, false, true, 2, 3, 2>(g_xnh, g_xnl, DIM_,
                                               g_wh[2], g_wl[2], INNER_,
                                               nullptr, nullptr, nullptr,
                                               g_vh, g_vl, INNER_, DIM_, nullptr, 1.f);
    } else {
        tgemm<bf16, 128, false, true, 2, 3, 2>(g_cnh, g_cnl, DIM_,
                                               g_wh[3], g_wl[3], INNER_,
                                               nullptr, nullptr, nullptr,
                                               g_cvh, g_cvl, INNER_, DIM_, nullptr, 1.f);
    }
}
// both output projections in ONE launch
__global__ void __launch_bounds__(256, 2) k_projF2(float* out,
                                                   const float* b_out,
                                                   const float* b_cout) {
    if (blockIdx.z == 0) {
        tgemm<bf16, 128, false, true, 2, 0, 2>(g_o1h, g_o1l, INNER_,
                                               g_wh[4], g_wl[4], DIM_,
                                               out, nullptr, nullptr, nullptr,
                                               nullptr, DIM_, INNER_, b_out, 1.f);
    } else {
        tgemm<bf16, 128, false, true, 2, 0, 2>(g_o2h, g_o2l, INNER_,
                                               g_wh[5], g_wl[5], DIM_,
                                               out + (size_t)B_ * I_ * DIM_,
                                               nullptr, nullptr, nullptr,
                                               nullptr, DIM_, INNER_, b_cout, 1.f);
    }
}
// sim: exp(scale*QK) -> fp16 + softmax stat partials (K=64 -> 2 stages)
__global__ void __launch_bounds__(256, 2) k_sim() {
    int z = blockIdx.z, b = z >> 4, h = z & 15;
    size_t qo = (size_t)b * I_ * INNER_ + h * DH_;
    size_t ko = (size_t)b * J_ * INNER_ + h * DH_;
    tgemm<bf16, 128, false, false, 2, 2, 2>(g_qkh + qo, g_qkl + qo, INNER_,
                                            g_ckh + ko, g_ckl + ko, INNER_,
                                            nullptr, nullptr, nullptr,
                                            g_sim16 + (size_t)z * I_ * J_, nullptr,
                                            J_, DH_, nullptr, SCALE_);
}
// both AV GEMMs in ONE launch (DRAM-streaming -> 3 stages)
__global__ void __launch_bounds__(256, 2) k_avx() {
    int z = blockIdx.z;
    if (z < NZ_) {
        int b = z >> 4, h = z & 15;
        size_t ao = (size_t)z * I_ * J_;
        size_t vo = (size_t)b * J_ * INNER_ + h * DH_;
        size_t oo = (size_t)b * I_ * INNER_ + h * DH_;
        tgemm<half, 64, false, true, 1, 1, 3>(g_at16 + ao, nullptr, J_,
                                              g_cvh + vo, g_cvl + vo, INNER_,
                                              nullptr, g_o1h + oo, g_o1l + oo,
                                              nullptr, nullptr, INNER_, J_,
                                              nullptr, 1.f);
    } else {
        int zz = z - NZ_;
        int b = zz >> 4, h = zz & 15;
        size_t ao = (size_t)zz * I_ * J_;
        size_t vo = (size_t)b * I_ * INNER_ + h * DH_;
        size_t oo = (size_t)b * J_ * INNER_ + h * DH_;
        tgemm<half, 64, true, true, 1, 1, 3>(g_ct16 + ao, nullptr, J_,
                                             g_vh + vo, g_vl + vo, INNER_,
                                             nullptr, g_o2h + oo, g_o2l + oo,
                                             nullptr, nullptr, INNER_, I_,
                                             nullptr, 1.f);
    }
}

// ---------------- stat partial reduction: 1/sum ----------------
__global__ void statreduce() {
    int idx = blockIdx.x * 256 + threadIdx.x;
    const float* src = blockIdx.y ? g_cp : g_rp;
    const float4* s4 = (const float4*)(src + (size_t)idx * 16);
    float4 a = s4[0], b = s4[1], c = s4[2], d = s4[3];
    float s = a.x + a.y + a.z + a.w + b.x + b.y + b.z + b.w
            + c.x + c.y + c.z + c.w + d.x + d.y + d.z + d.w;
    (blockIdx.y ? g_cs : g_rs)[idx] = 1.f / s;
}

// ------- fused softmax-normalize + talking-heads mix, 2 j per thread ------
__global__ void mix_kernel(const float* __restrict__ thw,
                           const float* __restrict__ cthw) {
    int b = blockIdx.z;
    int i = blockIdx.y;
    int t = threadIdx.x;
    int j = (blockIdx.x * 256 + t) * 2;

    __shared__ float wR[16][16], wC[16][16], ri[16];
    wR[t >> 4][t & 15] = thw[t];
    wC[t >> 4][t & 15] = cthw[t];
    if (t < 16) ri[t] = g_rs[((size_t)(b * H_ + t)) * I_ + i];
    __syncthreads();

    float2 pr[16], pc[16];
#pragma unroll
    for (int h = 0; h < 16; h++) {
        size_t zi = (size_t)(b * H_ + h);
        half2 e2 = *(const half2*)&g_sim16[(zi * I_ + i) * J_ + j];
        float2 e = __half22float2(e2);
        float rih = ri[h];
        float2 cv = *(const float2*)&g_cs[zi * J_ + j];
        pr[h].x = e.x * rih;   pr[h].y = e.y * rih;
        pc[h].x = e.x * cv.x;  pc[h].y = e.y * cv.y;
    }
#pragma unroll
    for (int g = 0; g < 16; g++) {
        float aR0 = 0.f, aR1 = 0.f, aC0 = 0.f, aC1 = 0.f;
#pragma unroll
        for (int h = 0; h < 16; h++) {
            float wr = wR[g][h], wc = wC[g][h];
            aR0 += wr * pr[h].x; aR1 += wr * pr[h].y;
            aC0 += wc * pc[h].x; aC1 += wc * pc[h].y;
        }
        size_t idx = (((size_t)(b * H_ + g)) * I_ + i) * J_ + j;
        *(half2*)&g_at16[idx] = __floats2half2_rn(aR0, aR1);
        *(half2*)&g_ct16[idx] = __floats2half2_rn(aC0, aC1);
    }
}

// ---------------- launch ----------------
extern "C" void kernel_launch(void* const* d_in, const int* in_sizes, int n_in,
                              void* d_out, int out_size) {
    const float* x     = (const float*)d_in[0];
    const float* ctx   = (const float*)d_in[1];
    const float* ln_g  = (const float*)d_in[2];
    const float* ln_b  = (const float*)d_in[3];
    const float* cln_g = (const float*)d_in[4];
    const float* cln_b = (const float*)d_in[5];
    const float* W_qk  = (const float*)d_in[6];
    const float* W_cqk = (const float*)d_in[7];
    const float* W_v   = (const float*)d_in[8];
    const float* W_cv  = (const float*)d_in[9];
    const float* W_out = (const float*)d_in[10];
    const float* b_out = (const float*)d_in[11];
    const float* W_cout= (const float*)d_in[12];
    const float* b_cout= (const float*)d_in[13];
    const float* thw   = (const float*)d_in[14];
    const float* cthw  = (const float*)d_in[15];
    float* out = (float*)d_out;

    bf16 *xnh, *xnl, *cnh, *cnl, *wh, *wl;
    cudaGetSymbolAddress((void**)&xnh, g_xnh); cudaGetSymbolAddress((void**)&xnl, g_xnl);
    cudaGetSymbolAddress((void**)&cnh, g_cnh); cudaGetSymbolAddress((void**)&cnl, g_cnl);
    cudaGetSymbolAddress((void**)&wh,  g_wh);  cudaGetSymbolAddress((void**)&wl,  g_wl);

    // smem sizes (bytes): proj/sim 2-stage, avx 3-stage
    constexpr int SM_PROJ = (2 * 2 * 128 * 40 + 2 * 2 * 32 * 136) * 2;  // 75776
    constexpr int SM_SIM  = (2 * 2 * 128 * 40 + 2 * 2 * 128 * 40) * 2;  // 81920
    constexpr int SM_AVX  = (1 * 3 * 128 * 40 + 2 * 3 * 32 * 72) * 2;   // 58368
    cudaFuncSetAttribute(k_proj4,  cudaFuncAttributeMaxDynamicSharedMemorySize, SM_PROJ);
    cudaFuncSetAttribute(k_projF2, cudaFuncAttributeMaxDynamicSharedMemorySize, SM_PROJ);
    cudaFuncSetAttribute(k_sim,    cudaFuncAttributeMaxDynamicSharedMemorySize, SM_SIM);
    cudaFuncSetAttribute(k_avx,    cudaFuncAttributeMaxDynamicSharedMemorySize, SM_AVX);

    // 1) layernorms + weight conversion
    ln_kernel<<<B_ * I_, 256>>>(x,   ln_g,  ln_b,  xnh, xnl);
    ln_kernel<<<B_ * J_, 256>>>(ctx, cln_g, cln_b, cnh, cnl);
    wconv_all<<<dim3(2048, 6), 256>>>(W_qk, W_cqk, W_v, W_cv, W_out, W_cout, wh, wl);

    // 2) all 4 input projections, single launch (2-stage)
    k_proj4<<<dim3(DIM_ / 128, (B_ * I_) / 128, 4), 256, SM_PROJ>>>();

    // 3) sim -> exp (fp16) + softmax stat partials
    k_sim<<<dim3(J_ / 128, I_ / 128, NZ_), 256, SM_SIM>>>();

    // 4) reduce partials -> 1/rowsum, 1/colsum
    statreduce<<<dim3(NZ_ * I_ / 256, 2), 256>>>();

    // 5) normalize + talking-heads mix -> fp16 attn planes
    mix_kernel<<<dim3(J_ / 512, I_, B_), 256>>>(thw, cthw);

    // 6) both attention-weighted-value GEMM families, single launch (3-stage)
    k_avx<<<dim3(1, I_ / 128, 2 * NZ_), 256, SM_AVX>>>();

    // 7) both output projections, single launch (2-stage)
    k_projF2<<<dim3(DIM_ / 128, (B_ * I_) / 128, 2), 256, SM_PROJ>>>(out, b_out, b_cout);
}

// round 16
// speedup vs baseline: 1.0500x; 1.0388x over previous
#include <cuda_runtime.h>
#include <cuda_bf16.h>
#include <cuda_fp16.h>
#include <stdint.h>
#include <math.h>

typedef __nv_bfloat16 bf16;

// ---------------- problem constants ----------------
#define B_     2
#define I_     2048
#define J_     2048
#define DIM_   1024
#define H_     16
#define DH_    64
#define INNER_ 1024
#define EPS_   1e-5f
#define SCALE_ 0.125f   // DH^-0.5
#define SIMN   134217728   // B*H*I*J
#define NZ_    32          // B*H

// ---------------- scratch (device globals; allocation-free) ----------------
__device__ bf16 g_xnh[B_ * I_ * DIM_],  g_xnl[B_ * I_ * DIM_];
__device__ bf16 g_cnh[B_ * J_ * DIM_],  g_cnl[B_ * J_ * DIM_];
__device__ bf16 g_qkh[B_ * I_ * INNER_], g_qkl[B_ * I_ * INNER_];
__device__ bf16 g_ckh[B_ * J_ * INNER_], g_ckl[B_ * J_ * INNER_];
__device__ half g_vh [B_ * I_ * INNER_], g_vl [B_ * I_ * INNER_];
__device__ half g_cvh[B_ * J_ * INNER_], g_cvl[B_ * J_ * INNER_];
__device__ bf16 g_o1h[B_ * I_ * INNER_], g_o1l[B_ * I_ * INNER_];
__device__ bf16 g_o2h[B_ * J_ * INNER_], g_o2l[B_ * J_ * INNER_];
__device__ bf16 g_wh[6][DIM_ * INNER_], g_wl[6][DIM_ * INNER_];
__device__ half g_sim16[SIMN];                // exp(scale*QK) fp16, 256 MB
__device__ half g_at16[SIMN], g_ct16[SIMN];   // mixed attn, fp16
__device__ float g_rp[NZ_ * I_ * 16], g_cp[NZ_ * J_ * 16];  // tile partial sums
__device__ float g_rs[NZ_ * I_], g_cs[NZ_ * J_];            // 1/rowsum, 1/colsum

// ---------------- helpers ----------------
__device__ __forceinline__ unsigned packsplit(float x, float y, unsigned& lo) {
    bf16 hx = __float2bfloat16(x);
    bf16 hy = __float2bfloat16(y);
    float lx = x - __bfloat162float(hx);
    float ly = y - __bfloat162float(hy);
    __nv_bfloat162 l2 = __floats2bfloat162_rn(lx, ly);
    lo = *(unsigned*)&l2;
    __nv_bfloat162 h2 = __halves2bfloat162(hx, hy);
    return *(unsigned*)&h2;
}
__device__ __forceinline__ unsigned packsplit_h(float x, float y, unsigned& lo) {
    half hx = __float2half(x);
    half hy = __float2half(y);
    float lx = x - __half2float(hx);
    float ly = y - __half2float(hy);
    half2 l2 = __floats2half2_rn(lx, ly);
    lo = *(unsigned*)&l2;
    half2 h2 = __halves2half2(hx, hy);
    return *(unsigned*)&h2;
}
template <class T> struct Mma;
template <> struct Mma<bf16> {
    static __device__ __forceinline__ void op(float* c, const unsigned* a,
                                              const unsigned* b) {
        asm volatile(
            "mma.sync.aligned.m16n8k16.row.col.f32.bf16.bf16.f32 "
            "{%0,%1,%2,%3}, {%4,%5,%6,%7}, {%8,%9}, {%0,%1,%2,%3};\n"
            : "+f"(c[0]), "+f"(c[1]), "+f"(c[2]), "+f"(c[3])
            : "r"(a[0]), "r"(a[1]), "r"(a[2]), "r"(a[3]), "r"(b[0]), "r"(b[1]));
    }
};
template <> struct Mma<half> {
    static __device__ __forceinline__ void op(float* c, const unsigned* a,
                                              const unsigned* b) {
        asm volatile(
            "mma.sync.aligned.m16n8k16.row.col.f32.f16.f16.f32 "
            "{%0,%1,%2,%3}, {%4,%5,%6,%7}, {%8,%9}, {%0,%1,%2,%3};\n"
            : "+f"(c[0]), "+f"(c[1]), "+f"(c[2]), "+f"(c[3])
            : "r"(a[0]), "r"(a[1]), "r"(a[2]), "r"(a[3]), "r"(b[0]), "r"(b[1]));
    }
};
__device__ __forceinline__ void ldsm4(unsigned* d, unsigned a) {
    asm volatile("ldmatrix.sync.aligned.m8n8.x4.shared.b16 {%0,%1,%2,%3},[%4];\n"
                 : "=r"(d[0]), "=r"(d[1]), "=r"(d[2]), "=r"(d[3]) : "r"(a));
}
__device__ __forceinline__ void ldsm4t(unsigned* d, unsigned a) {
    asm volatile("ldmatrix.sync.aligned.m8n8.x4.trans.shared.b16 {%0,%1,%2,%3},[%4];\n"
                 : "=r"(d[0]), "=r"(d[1]), "=r"(d[2]), "=r"(d[3]) : "r"(a));
}
__device__ __forceinline__ void cp16(void* smp, const void* gp) {
    unsigned sa = (unsigned)__cvta_generic_to_shared(smp);
    asm volatile("cp.async.cg.shared.global [%0], [%1], 16;\n" :: "r"(sa), "l"(gp));
}
__device__ __forceinline__ unsigned shaddr(const void* p) {
    return (unsigned)__cvta_generic_to_shared(p);
}

// ---------------- LayerNorm -> bf16 hi/lo planes ----------------
__global__ void ln_kernel(const float* __restrict__ x,
                          const float* __restrict__ gw,
                          const float* __restrict__ bw,
                          bf16* __restrict__ oh, bf16* __restrict__ ol) {
    int row = blockIdx.x;
    const float* xr = x + (size_t)row * DIM_;
    int t = threadIdx.x;
    int c = t * 4;

    float4 v = *(const float4*)(xr + c);
    float s = v.x + v.y + v.z + v.w;
    float sq = v.x * v.x + v.y * v.y + v.z * v.z + v.w * v.w;
    __shared__ float sh[64];
#pragma unroll
    for (int o = 16; o > 0; o >>= 1) {
        s  += __shfl_down_sync(0xffffffffu, s,  o);
        sq += __shfl_down_sync(0xffffffffu, sq, o);
    }
    if ((t & 31) == 0) { sh[t >> 5] = s; sh[32 + (t >> 5)] = sq; }
    __syncthreads();
    if (t < 32) {
        float a  = (t < 8) ? sh[t]      : 0.f;
        float b2 = (t < 8) ? sh[32 + t] : 0.f;
#pragma unroll
        for (int o = 4; o > 0; o >>= 1) {
            a  += __shfl_down_sync(0xffffffffu, a,  o);
            b2 += __shfl_down_sync(0xffffffffu, b2, o);
        }
        if (t == 0) { sh[0] = a; sh[1] = b2; }
    }
    __syncthreads();
    float mu   = sh[0] * (1.f / DIM_);
    float var  = sh[1] * (1.f / DIM_) - mu * mu;
    float rstd = rsqrtf(var + EPS_);
    float y0 = (v.x - mu) * rstd * gw[c + 0] + bw[c + 0];
    float y1 = (v.y - mu) * rstd * gw[c + 1] + bw[c + 1];
    float y2 = (v.z - mu) * rstd * gw[c + 2] + bw[c + 2];
    float y3 = (v.w - mu) * rstd * gw[c + 3] + bw[c + 3];
    size_t o0 = (size_t)row * DIM_ + c;
    unsigned lo, hi;
    hi = packsplit(y0, y1, lo);
    *(unsigned*)&oh[o0] = hi; *(unsigned*)&ol[o0] = lo;
    hi = packsplit(y2, y3, lo);
    *(unsigned*)&oh[o0 + 2] = hi; *(unsigned*)&ol[o0 + 2] = lo;
}

// ---------------- all 6 weights fp32 -> bf16 hi/lo, single launch ---------
__global__ void wconv_all(const float* __restrict__ w0, const float* __restrict__ w1,
                          const float* __restrict__ w2, const float* __restrict__ w3,
                          const float* __restrict__ w4, const float* __restrict__ w5,
                          bf16* __restrict__ Wh, bf16* __restrict__ Wl) {
    const float* srcs[6] = {w0, w1, w2, w3, w4, w5};
    int w = blockIdx.y;
    const float* W = srcs[w];
    size_t base = (size_t)w * DIM_ * INNER_;
    size_t i = ((size_t)blockIdx.x * 256 + threadIdx.x) * 2;
    float2 v = *(const float2*)(W + i);
    unsigned lo, hi = packsplit(v.x, v.y, lo);
    *(unsigned*)&Wh[base + i] = hi;
    *(unsigned*)&Wl[base + i] = lo;
}

// ================= hi/lo split tensor-core GEMM (NSTAGE-deep cp.async) ====
// DT: bf16 or half.  A: ATR ? [K][M] : [M][K].  B: BKN ? [K][N] : [N][K].
// APL/BPL: # of A/B planes.  OMODE: 0 fp32+bias; 1 bf16 planes; 2 exp->fp16
// sim + softmax stat partials; 3 fp16 planes.
template <class DT, int BN, bool ATR, bool BKN, int APL, int BPL, int OMODE,
          int NSTAGE>
__device__ __forceinline__ void tgemm(const DT* __restrict__ Ah,
                                      const DT* __restrict__ Al, int lda,
                                      const DT* __restrict__ Bh,
                                      const DT* __restrict__ Bl, int ldb,
                                      float* __restrict__ C,
                                      bf16* __restrict__ Ch,
                                      bf16* __restrict__ Cl,
                                      half* __restrict__ Fh,
                                      half* __restrict__ Fl,
                                      int ldc, int K,
                                      const float* __restrict__ bias,
                                      float alpha) {
    constexpr int BM = 128, BK = 32;
    constexpr int SAS = ATR ? (BM + 8) : (BK + 8);
    constexpr int SBS = BKN ? (BN + 8) : (BK + 8);
    constexpr int ASZ = (ATR ? BK : BM) * SAS;
    constexpr int BSZ = (BKN ? BK : BN) * SBS;
    constexpr int NT8 = BN / 16;
    constexpr int NG  = BN / 32;
    constexpr int CB  = BN * 4;

    extern __shared__ unsigned char smraw[];
    DT* sm = (DT*)smraw;
    const int t = threadIdx.x, lane = t & 31, warp = t >> 5;
    const int gi = lane >> 2, gj = lane & 3;
    const int wm = (warp >> 1) * 32, wn = (warp & 1) * (BN / 2);
    const int m0 = blockIdx.y * BM, n0 = blockIdx.x * BN;

    float acc[2][NT8][4];
#pragma unroll
    for (int a = 0; a < 2; a++)
#pragma unroll
        for (int b = 0; b < NT8; b++)
#pragma unroll
            for (int q = 0; q < 4; q++) acc[a][b][q] = 0.f;

    auto cpA = [&](int kc, int st) {
#pragma unroll
        for (int p = 0; p < APL; p++) {
            const DT* src = p ? Al : Ah;
            DT* dst = sm + (p * NSTAGE + st) * ASZ;
            if (!ATR) {
#pragma unroll
                for (int q = t; q < 512; q += 256) {
                    int row = q >> 2, c = (q & 3) * 8;
                    cp16(dst + row * SAS + c,
                         src + (size_t)(m0 + row) * lda + kc * BK + c);
                }
            } else {
#pragma unroll
                for (int q = t; q < 512; q += 256) {
                    int row = q >> 4, c = (q & 15) * 8;
                    cp16(dst + row * SAS + c,
                         src + (size_t)(kc * BK + row) * lda + m0 + c);
                }
            }
        }
    };
    auto cpB = [&](int kc, int st) {
#pragma unroll
        for (int p = 0; p < BPL; p++) {
            const DT* src = p ? Bl : Bh;
            DT* dst = sm + APL * NSTAGE * ASZ + (p * NSTAGE + st) * BSZ;
            if (BKN) {
#pragma unroll
                for (int q = t; q < CB; q += 256) {
                    int row = q / (BN / 8), c = (q % (BN / 8)) * 8;
                    cp16(dst + row * SBS + c,
                         src + (size_t)(kc * BK + row) * ldb + n0 + c);
                }
            } else {
#pragma unroll
                for (int q = t; q < CB; q += 256) {
                    int row = q >> 2, c = (q & 3) * 8;
                    cp16(dst + row * SBS + c,
                         src + (size_t)(n0 + row) * ldb + kc * BK + c);
                }
            }
        }
    };

    const int NK = K / BK;
#pragma unroll
    for (int s = 0; s < NSTAGE - 1; s++) {
        cpA(s, s); cpB(s, s);
        asm volatile("cp.async.commit_group;\n");
    }

    int st = 0, pfst = NSTAGE - 1;
    for (int kc = 0; kc < NK; kc++) {
        int pf = kc + NSTAGE - 1;
        if (pf < NK) {
            cpA(pf, pfst); cpB(pf, pfst);
            asm volatile("cp.async.commit_group;\n");
            asm volatile("cp.async.wait_group %0;\n" :: "n"(NSTAGE - 1));
        } else {
            asm volatile("cp.async.wait_group 0;\n");
        }
        __syncthreads();

        const DT* sAh = sm + st * ASZ;
        const DT* sAl = sm + (NSTAGE + st) * ASZ;
        const DT* sBh = sm + APL * NSTAGE * ASZ + st * BSZ;
        const DT* sBl = sm + APL * NSTAGE * ASZ + (NSTAGE + st) * BSZ;

#pragma unroll
        for (int ks = 0; ks < 2; ks++) {
            const int kofs = ks * 16;
            unsigned aH[2][4], aL[2][4];
            if (!ATR) {
                int r = lane & 15, c = (lane >> 4) * 8;
#pragma unroll
                for (int mt = 0; mt < 2; mt++) {
                    int off = (wm + mt * 16 + r) * SAS + kofs + c;
                    ldsm4(aH[mt], shaddr(sAh + off));
                    if (APL == 2) ldsm4(aL[mt], shaddr(sAl + off));
                }
            } else {
                int kr = kofs + (lane & 7) + ((lane >> 4) << 3);
#pragma unroll
                for (int mt = 0; mt < 2; mt++) {
                    int mc = wm + mt * 16 + (lane & 8);
                    int off = kr * SAS + mc;
                    ldsm4t(aH[mt], shaddr(sAh + off));
                    if (APL == 2) ldsm4t(aL[mt], shaddr(sAl + off));
                }
            }
#pragma unroll
            for (int g = 0; g < NG; g++) {
                unsigned bH[4], bL[4];
                int nb = wn + g * 16;
                if (BKN) {
                    int kr = kofs + (lane & 7) + ((lane & 8) ? 8 : 0);
                    int nc = nb + ((lane & 16) ? 8 : 0);
                    int off = kr * SBS + nc;
                    ldsm4t(bH, shaddr(sBh + off));
                    if (BPL == 2) ldsm4t(bL, shaddr(sBl + off));
                } else {
                    int nr = nb + (lane & 7) + ((lane & 16) ? 8 : 0);
                    int kc2 = kofs + ((lane & 8) ? 8 : 0);
                    int off = nr * SBS + kc2;
                    ldsm4(bH, shaddr(sBh + off));
                    if (BPL == 2) ldsm4(bL, shaddr(sBl + off));
                }
#pragma unroll
                for (int mt = 0; mt < 2; mt++) {
                    Mma<DT>::op(acc[mt][2 * g], aH[mt], bH);
                    if (BPL == 2) Mma<DT>::op(acc[mt][2 * g], aH[mt], bL);
                    if (APL == 2) Mma<DT>::op(acc[mt][2 * g], aL[mt], bH);
                    Mma<DT>::op(acc[mt][2 * g + 1], aH[mt], bH + 2);
                    if (BPL == 2) Mma<DT>::op(acc[mt][2 * g + 1], aH[mt], bL + 2);
                    if (APL == 2) Mma<DT>::op(acc[mt][2 * g + 1], aL[mt], bH + 2);
                }
            }
        }
        __syncthreads();
        st   = (st + 1 == NSTAGE) ? 0 : st + 1;
        pfst = (pfst + 1 == NSTAGE) ? 0 : pfst + 1;
    }

    if constexpr (OMODE == 2) {
        // exp -> fp16 sim (smem-staged coalesced store) + softmax partials
        __shared__ float rsm[2][128];
        __shared__ float csm[4][128];
        constexpr int SCS = 136;
        half* sc = (half*)smraw;
        float rsum[2][2] = {};
        float csum[NT8][2] = {};
#pragma unroll
        for (int mt = 0; mt < 2; mt++)
#pragma unroll
            for (int nt = 0; nt < NT8; nt++) {
                int r = wm + mt * 16 + gi;
                int c = wn + nt * 8 + 2 * gj;
                float e0 = __expf(acc[mt][nt][0] * alpha);
                float e1 = __expf(acc[mt][nt][1] * alpha);
                float e2 = __expf(acc[mt][nt][2] * alpha);
                float e3 = __expf(acc[mt][nt][3] * alpha);
                *(half2*)&sc[r * SCS + c]       = __floats2half2_rn(e0, e1);
                *(half2*)&sc[(r + 8) * SCS + c] = __floats2half2_rn(e2, e3);
                rsum[mt][0] += e0 + e1;
                rsum[mt][1] += e2 + e3;
                csum[nt][0] += e0 + e2;
                csum[nt][1] += e1 + e3;
            }
#pragma unroll
        for (int mt = 0; mt < 2; mt++)
#pragma unroll
            for (int rh = 0; rh < 2; rh++) {
                float v = rsum[mt][rh];
                v += __shfl_xor_sync(0xffffffffu, v, 1);
                v += __shfl_xor_sync(0xffffffffu, v, 2);
                if (gj == 0) rsm[warp & 1][wm + mt * 16 + gi + rh * 8] = v;
            }
#pragma unroll
        for (int nt = 0; nt < NT8; nt++)
#pragma unroll
            for (int q = 0; q < 2; q++) {
                float v = csum[nt][q];
                v += __shfl_xor_sync(0xffffffffu, v, 4);
                v += __shfl_xor_sync(0xffffffffu, v, 8);
                v += __shfl_xor_sync(0xffffffffu, v, 16);
                if (gi == 0) csm[warp >> 1][wn + nt * 8 + 2 * gj + q] = v;
            }
        __syncthreads();
#pragma unroll
        for (int it = 0; it < 8; it++) {
            int row = (t >> 4) + it * 16;
            int ch = t & 15;
            uint4 vv = *(uint4*)&sc[row * SCS + ch * 8];
            *(uint4*)&Fh[(size_t)(m0 + row) * ldc + n0 + ch * 8] = vv;
        }
        if (t < 128) {
            float rtot = rsm[0][t] + rsm[1][t];
            g_rp[((size_t)blockIdx.z * I_ + m0 + t) * 16 + blockIdx.x] = rtot;
            float ctot = csm[0][t] + csm[1][t] + csm[2][t] + csm[3][t];
            g_cp[((size_t)blockIdx.z * J_ + n0 + t) * 16 + blockIdx.y] = ctot;
        }
        return;
    }

#pragma unroll
    for (int mt = 0; mt < 2; mt++)
#pragma unroll
        for (int nt = 0; nt < NT8; nt++) {
            int r = m0 + wm + mt * 16 + gi;
            int c = n0 + wn + nt * 8 + 2 * gj;
            const float* a = acc[mt][nt];
            if constexpr (OMODE == 0) {
                float b0 = bias ? bias[c] : 0.f;
                float b1 = bias ? bias[c + 1] : 0.f;
                float2 v0 = {a[0] * alpha + b0, a[1] * alpha + b1};
                float2 v1 = {a[2] * alpha + b0, a[3] * alpha + b1};
                *(float2*)&C[(size_t)r * ldc + c] = v0;
                *(float2*)&C[(size_t)(r + 8) * ldc + c] = v1;
            } else if constexpr (OMODE == 1) {
                unsigned lo, hi;
                hi = packsplit(a[0], a[1], lo);
                *(unsigned*)&Ch[(size_t)r * ldc + c] = hi;
                *(unsigned*)&Cl[(size_t)r * ldc + c] = lo;
                hi = packsplit(a[2], a[3], lo);
                *(unsigned*)&Ch[(size_t)(r + 8) * ldc + c] = hi;
                *(unsigned*)&Cl[(size_t)(r + 8) * ldc + c] = lo;
            } else {   // OMODE == 3
                unsigned lo, hi;
                hi = packsplit_h(a[0], a[1], lo);
                *(unsigned*)&Fh[(size_t)r * ldc + c] = hi;
                *(unsigned*)&Fl[(size_t)r * ldc + c] = lo;
                hi = packsplit_h(a[2], a[3], lo);
                *(unsigned*)&Fh[(size_t)(r + 8) * ldc + c] = hi;
                *(unsigned*)&Fl[(size_t)(r + 8) * ldc + c] = lo;
            }
        }
}

// ---- kernel wrappers (all capped for 2 CTAs/SM) ----
// all 4 input projections in ONE launch; z selects {Q, ctxQ, V, ctxV}
__global__ void __launch_bounds__(256, 2) k_proj4() {
    int z = blockIdx.z;
    if (z == 0) {
        tgemm<bf16, 128, false, true, 2, 2, 1, 2>(g_xnh, g_xnl, DIM_,
                                                  g_wh[0], g_wl[0], INNER_,
                                                  nullptr, g_qkh, g_qkl, nullptr,
                                                  nullptr, INNER_, DIM_, nullptr, 1.f);
    } else if (z == 1) {
        tgemm<bf16, 128, false, true, 2, 2, 1, 2>(g_cnh, g_cnl, DIM_,
                                                  g_wh[1], g_wl[1], INNER_,
                                                  nullptr, g_ckh, g_ckl, nullptr,
                                                  nullptr, INNER_, DIM_, nullptr, 1.f);
    } else if (z == 2) {
        tgemm<bf16, 128, false, true, 2, 2, 3, 2>(g_xnh, g_xnl, DIM_,
                                                  g_wh[2], g_wl[2], INNER_,
                                                  nullptr, nullptr, nullptr,
                                                  g_vh, g_vl, INNER_, DIM_, nullptr, 1.f);
    } else {
        tgemm<bf16, 128, false, true, 2, 2, 3, 2>(g_cnh, g_cnl, DIM_,
                                                  g_wh[3], g_wl[3], INNER_,
                                                  nullptr, nullptr, nullptr,
                                                  g_cvh, g_cvl, INNER_, DIM_, nullptr, 1.f);
    }
}
// both output projections in ONE launch
__global__ void __launch_bounds__(256, 2) k_projF2(float* out,
                                                   const float* b_out,
                                                   const float* b_cout) {
    if (blockIdx.z == 0) {
        tgemm<bf16, 128, false, true, 2, 2, 0, 2>(g_o1h, g_o1l, INNER_,
                                                  g_wh[4], g_wl[4], DIM_,
                                                  out, nullptr, nullptr, nullptr,
                                                  nullptr, DIM_, INNER_, b_out, 1.f);
    } else {
        tgemm<bf16, 128, false, true, 2, 2, 0, 2>(g_o2h, g_o2l, INNER_,
                                                  g_wh[5], g_wl[5], DIM_,
                                                  out + (size_t)B_ * I_ * DIM_,
                                                  nullptr, nullptr, nullptr,
                                                  nullptr, DIM_, INNER_, b_cout, 1.f);
    }
}
// sim: exp(scale*QK) -> fp16 + softmax stat partials
__global__ void __launch_bounds__(256, 2) k_sim() {
    int z = blockIdx.z, b = z >> 4, h = z & 15;
    size_t qo = (size_t)b * I_ * INNER_ + h * DH_;
    size_t ko = (size_t)b * J_ * INNER_ + h * DH_;
    tgemm<bf16, 128, false, false, 2, 2, 2, 2>(g_qkh + qo, g_qkl + qo, INNER_,
                                               g_ckh + ko, g_ckl + ko, INNER_,
                                               nullptr, nullptr, nullptr,
                                               g_sim16 + (size_t)z * I_ * J_, nullptr,
                                               J_, DH_, nullptr, SCALE_);
}
// both AV GEMMs in ONE launch (single-plane V: attn fp16 x Vh fp16)
__global__ void __launch_bounds__(256, 2) k_avx() {
    int z = blockIdx.z;
    if (z < NZ_) {
        int b = z >> 4, h = z & 15;
        size_t ao = (size_t)z * I_ * J_;
        size_t vo = (size_t)b * J_ * INNER_ + h * DH_;
        size_t oo = (size_t)b * I_ * INNER_ + h * DH_;
        tgemm<half, 64, false, true, 1, 1, 1, 3>(g_at16 + ao, nullptr, J_,
                                                 g_cvh + vo, nullptr, INNER_,
                                                 nullptr, g_o1h + oo, g_o1l + oo,
                                                 nullptr, nullptr, INNER_, J_,
                                                 nullptr, 1.f);
    } else {
        int zz = z - NZ_;
        int b = zz >> 4, h = zz & 15;
        size_t ao = (size_t)zz * I_ * J_;
        size_t vo = (size_t)b * I_ * INNER_ + h * DH_;
        size_t oo = (size_t)b * J_ * INNER_ + h * DH_;
        tgemm<half, 64, true, true, 1, 1, 1, 3>(g_ct16 + ao, nullptr, J_,
                                                g_vh + vo, nullptr, INNER_,
                                                nullptr, g_o2h + oo, g_o2l + oo,
                                                nullptr, nullptr, INNER_, I_,
                                                nullptr, 1.f);
    }
}

// ---------------- stat partial reduction: 1/sum ----------------
__global__ void statreduce() {
    int idx = blockIdx.x * 256 + threadIdx.x;
    const float* src = blockIdx.y ? g_cp : g_rp;
    const float4* s4 = (const float4*)(src + (size_t)idx * 16);
    float4 a = s4[0], b = s4[1], c = s4[2], d = s4[3];
    float s = a.x + a.y + a.z + a.w + b.x + b.y + b.z + b.w
            + c.x + c.y + c.z + c.w + d.x + d.y + d.z + d.w;
    (blockIdx.y ? g_cs : g_rs)[idx] = 1.f / s;
}

// ------- fused softmax-normalize + talking-heads mix, 2 j per thread ------
__global__ void mix_kernel(const float* __restrict__ thw,
                           const float* __restrict__ cthw) {
    int b = blockIdx.z;
    int i = blockIdx.y;
    int t = threadIdx.x;
    int j = (blockIdx.x * 256 + t) * 2;

    __shared__ float wR[16][16], wC[16][16], ri[16];
    wR[t >> 4][t & 15] = thw[t];
    wC[t >> 4][t & 15] = cthw[t];
    if (t < 16) ri[t] = g_rs[((size_t)(b * H_ + t)) * I_ + i];
    __syncthreads();

    float2 pr[16], pc[16];
#pragma unroll
    for (int h = 0; h < 16; h++) {
        size_t zi = (size_t)(b * H_ + h);
        half2 e2 = *(const half2*)&g_sim16[(zi * I_ + i) * J_ + j];
        float2 e = __half22float2(e2);
        float rih = ri[h];
        float2 cv = *(const float2*)&g_cs[zi * J_ + j];
        pr[h].x = e.x * rih;   pr[h].y = e.y * rih;
        pc[h].x = e.x * cv.x;  pc[h].y = e.y * cv.y;
    }
#pragma unroll
    for (int g = 0; g < 16; g++) {
        float aR0 = 0.f, aR1 = 0.f, aC0 = 0.f, aC1 = 0.f;
#pragma unroll
        for (int h = 0; h < 16; h++) {
            float wr = wR[g][h], wc = wC[g][h];
            aR0 += wr * pr[h].x; aR1 += wr * pr[h].y;
            aC0 += wc * pc[h].x; aC1 += wc * pc[h].y;
        }
        size_t idx = (((size_t)(b * H_ + g)) * I_ + i) * J_ + j;
        *(half2*)&g_at16[idx] = __floats2half2_rn(aR0, aR1);
        *(half2*)&g_ct16[idx] = __floats2half2_rn(aC0, aC1);
    }
}

// ---------------- launch ----------------
extern "C" void kernel_launch(void* const* d_in, const int* in_sizes, int n_in,
                              void* d_out, int out_size) {
    const float* x     = (const float*)d_in[0];
    const float* ctx   = (const float*)d_in[1];
    const float* ln_g  = (const float*)d_in[2];
    const float* ln_b  = (const float*)d_in[3];
    const float* cln_g = (const float*)d_in[4];
    const float* cln_b = (const float*)d_in[5];
    const float* W_qk  = (const float*)d_in[6];
    const float* W_cqk = (const float*)d_in[7];
    const float* W_v   = (const float*)d_in[8];
    const float* W_cv  = (const float*)d_in[9];
    const float* W_out = (const float*)d_in[10];
    const float* b_out = (const float*)d_in[11];
    const float* W_cout= (const float*)d_in[12];
    const float* b_cout= (const float*)d_in[13];
    const float* thw   = (const float*)d_in[14];
    const float* cthw  = (const float*)d_in[15];
    float* out = (float*)d_out;

    bf16 *xnh, *xnl, *cnh, *cnl, *wh, *wl;
    cudaGetSymbolAddress((void**)&xnh, g_xnh); cudaGetSymbolAddress((void**)&xnl, g_xnl);
    cudaGetSymbolAddress((void**)&cnh, g_cnh); cudaGetSymbolAddress((void**)&cnl, g_cnl);
    cudaGetSymbolAddress((void**)&wh,  g_wh);  cudaGetSymbolAddress((void**)&wl,  g_wl);

    // smem sizes (bytes): proj/sim/projF 2-stage, avx 3-stage single-B-plane
    constexpr int SM_PROJ = (2 * 2 * 128 * 40 + 2 * 2 * 32 * 136) * 2;  // 75776
    constexpr int SM_SIM  = (2 * 2 * 128 * 40 + 2 * 2 * 128 * 40) * 2;  // 81920
    constexpr int SM_AVX  = (1 * 3 * 128 * 40 + 1 * 3 * 32 * 72) * 2;   // 44544
    cudaFuncSetAttribute(k_proj4,  cudaFuncAttributeMaxDynamicSharedMemorySize, SM_PROJ);
    cudaFuncSetAttribute(k_projF2, cudaFuncAttributeMaxDynamicSharedMemorySize, SM_PROJ);
    cudaFuncSetAttribute(k_sim,    cudaFuncAttributeMaxDynamicSharedMemorySize, SM_SIM);
    cudaFuncSetAttribute(k_avx,    cudaFuncAttributeMaxDynamicSharedMemorySize, SM_AVX);

    // 1) layernorms + weight conversion
    ln_kernel<<<B_ * I_, 256>>>(x,   ln_g,  ln_b,  xnh, xnl);
    ln_kernel<<<B_ * J_, 256>>>(ctx, cln_g, cln_b, cnh, cnl);
    wconv_all<<<dim3(2048, 6), 256>>>(W_qk, W_cqk, W_v, W_cv, W_out, W_cout, wh, wl);

    // 2) all 4 input projections, single launch (2-stage)
    k_proj4<<<dim3(DIM_ / 128, (B_ * I_) / 128, 4), 256, SM_PROJ>>>();

    // 3) sim -> exp (fp16) + softmax stat partials
    k_sim<<<dim3(J_ / 128, I_ / 128, NZ_), 256, SM_SIM>>>();

    // 4) reduce partials -> 1/rowsum, 1/colsum
    statreduce<<<dim3(NZ_ * I_ / 256, 2), 256>>>();

    // 5) normalize + talking-heads mix -> fp16 attn planes
    mix_kernel<<<dim3(J_ / 512, I_, B_), 256>>>(thw, cthw);

    // 6) both attention-weighted-value GEMM families, single launch (3-stage)
    k_avx<<<dim3(1, I_ / 128, 2 * NZ_), 256, SM_AVX>>>();

    // 7) both output projections, single launch (2-stage)
    k_projF2<<<dim3(DIM_ / 128, (B_ * I_) / 128, 2), 256, SM_PROJ>>>(out, b_out, b_cout);
}